// round 11
// baseline (speedup 1.0000x reference)
#include <cuda_runtime.h>
#include <cuda_fp16.h>
#include <cstdint>

// ============================================================================
// DenseAttention via Gram reassociation:
//   G[b,q]  = X_{b,q}^T X_{b,q}             (symmetric => compute 3 of 4 tiles)
//   T[b,a,q]= (1024*W_{a,q}) @ G[b,q]
//   Pq      = T @ (1024*C_{a,q})^T-layout ;  P = 2^-10 * sum_q Pq
//   out     = 2^-10 * X_{b,a} @ P[b,a]
// Single-pass fp16, fp32 accumulate (rel_err 5.25e-4, calibrated).
// R11: s4 -> 128x256 tiles (single wave, 128 CTAs); s23 load reorder hides
// phase-2 Ct loads under phase-1 compute.
// ============================================================================

#define HH 65536

// ---------------- scratch (static device globals; no allocation) ------------
__device__ __align__(256) __half g_Xt[8 * 256 * 2048];      // [bq][f][t]
__device__ __align__(256) __half g_Xnt[2 * 2048 * 1024];    // [b][t][e]
__device__ __align__(256) __half g_Wc[16 * HH];             // [aq][e][f] *1024
__device__ __align__(256) __half g_Ct[16 * HH];             // [aq][g'][g] *1024
__device__ __align__(256) float  g_Gpart[6 * 8 * 3 * 16384];// [chunk][bq][tile]
__device__ __align__(256) __half g_G[8 * HH];               // [bq][f][g]
__device__ __align__(256) float  g_Pq[32 * HH];              // [baq][e][g']
__device__ __align__(256) __half g_Pt[8 * HH];              // [ba][g'][e]

// ---------------- PTX helpers ------------------------------------------------
__device__ __forceinline__ uint32_t smem_u32(const void* p) {
    uint32_t a;
    asm("{ .reg .u64 t; cvta.to.shared.u64 t, %1; cvt.u32.u64 %0, t; }" : "=r"(a) : "l"(p));
    return a;
}
__device__ __forceinline__ void cpa16(uint32_t s, const void* g) {
    asm volatile("cp.async.cg.shared.global [%0], [%1], 16;" :: "r"(s), "l"(g));
}
#define CP_COMMIT() asm volatile("cp.async.commit_group;" ::: "memory")
#define CP_WAIT(n)  asm volatile("cp.async.wait_group %0;" :: "n"(n) : "memory")

#define LDSM_X4(r, addr) \
    asm volatile("ldmatrix.sync.aligned.m8n8.x4.shared.b16 {%0,%1,%2,%3}, [%4];" \
        : "=r"((r)[0]), "=r"((r)[1]), "=r"((r)[2]), "=r"((r)[3]) : "r"(addr))

#define MMA_F16(d, a, b0, b1) \
    asm volatile("mma.sync.aligned.m16n8k16.row.col.f32.f16.f16.f32 " \
        "{%0,%1,%2,%3}, {%4,%5,%6,%7}, {%8,%9}, {%0,%1,%2,%3};" \
        : "+f"((d)[0]), "+f"((d)[1]), "+f"((d)[2]), "+f"((d)[3]) \
        : "r"((a)[0]), "r"((a)[1]), "r"((a)[2]), "r"((a)[3]), "r"(b0), "r"(b1))

__device__ __forceinline__ uint2 pack4H(float4 v) {
    union { __half b[4]; uint2 u; } Hq;
    Hq.b[0] = __float2half_rn(v.x); Hq.b[1] = __float2half_rn(v.y);
    Hq.b[2] = __float2half_rn(v.z); Hq.b[3] = __float2half_rn(v.w);
    return Hq.u;
}

// ============================================================================
// Generic 128x128 tile GEMM (s1): 256 threads, 8 warps 4Mx2N (32x64 warp
// tile), BK=128 double-buffered cp.async, fp16 single-pass, fp32 accum.
// ============================================================================
#define ROWB   272
#define T_A    0
#define T_B    34816
#define BUFSZ  69632
#define SMEM_G (2 * BUFSZ)

__device__ __forceinline__ void gemm128(
    const __half* __restrict__ A, int lda,
    const __half* __restrict__ B, int ldb,
    int K, float* __restrict__ Cf, int ldc, float outScale)
{
    extern __shared__ char smem[];
    const uint32_t sb  = smem_u32(smem);
    const int tid  = threadIdx.x;
    const int lane = tid & 31;
    const int wid  = tid >> 5;
    const int m0   = (wid >> 1) * 32;
    const int n0   = (wid & 1) * 64;

    const uint32_t aoff = (uint32_t)(m0 + (lane & 15)) * ROWB + ((lane >> 4) << 4);
    const uint32_t boff = (uint32_t)(n0 + ((lane >> 4) << 3) + (lane & 7)) * ROWB
                        + ((lane & 8) ? 16u : 0u);

    float acc[2][8][4];
#pragma unroll
    for (int i = 0; i < 2; i++)
#pragma unroll
        for (int j = 0; j < 8; j++)
#pragma unroll
            for (int r = 0; r < 4; r++) acc[i][j][r] = 0.0f;

    auto load_chunk = [&](int c) {
        const uint32_t bo = sb + (uint32_t)(c & 1) * BUFSZ;
        const int k0 = c << 7;
#pragma unroll
        for (int i = 0; i < 8; i++) {
            int v = i * 256 + tid;
            int r = v >> 4, j = v & 15;
            uint32_t so = (uint32_t)r * ROWB + (uint32_t)j * 16;
            cpa16(bo + T_A + so, A + (size_t)r * lda + k0 + j * 8);
            cpa16(bo + T_B + so, B + (size_t)r * ldb + k0 + j * 8);
        }
    };

    const int NC = K >> 7;
    load_chunk(0);
    CP_COMMIT();

#pragma unroll 1
    for (int c = 0; c < NC; c++) {
        if (c < NC - 1) { load_chunk(c + 1); CP_COMMIT(); CP_WAIT(1); }
        else            { CP_WAIT(0); }
        __syncthreads();

        const uint32_t bo = sb + (uint32_t)(c & 1) * BUFSZ;
        const uint32_t aP = bo + T_A + aoff;
        const uint32_t bP = bo + T_B + boff;

#pragma unroll
        for (int ks = 0; ks < 8; ks++) {
            const uint32_t ko = (uint32_t)ks * 32;
            uint32_t a0[4], a1[4];
            LDSM_X4(a0, aP + ko);
            LDSM_X4(a1, aP + 16 * ROWB + ko);
            uint32_t br[4][4];
#pragma unroll
            for (int p = 0; p < 4; p++)
                LDSM_X4(br[p], bP + (uint32_t)p * 16 * ROWB + ko);
#pragma unroll
            for (int j = 0; j < 8; j++)
                MMA_F16(acc[0][j], a0, br[j >> 1][(j & 1) * 2], br[j >> 1][(j & 1) * 2 + 1]);
#pragma unroll
            for (int j = 0; j < 8; j++)
                MMA_F16(acc[1][j], a1, br[j >> 1][(j & 1) * 2], br[j >> 1][(j & 1) * 2 + 1]);
        }
        __syncthreads();
    }

    const int rr = lane >> 2;
    const int cc = (lane & 3) * 2;
#pragma unroll
    for (int i = 0; i < 2; i++) {
#pragma unroll
        for (int j = 0; j < 8; j++) {
            const int row = m0 + i * 16 + rr;
            const int col = n0 + j * 8 + cc;
            float* p = Cf + (size_t)row * ldc + col;
            *(float2*)p = make_float2(acc[i][j][0] * outScale, acc[i][j][1] * outScale);
            *(float2*)(p + (size_t)8 * ldc) =
                make_float2(acc[i][j][2] * outScale, acc[i][j][3] * outScale);
        }
    }
}

// ============================================================================
// FUSED s2+s3 kernel: 64x256 tiles, 256 threads (8 warps: 2M x 4N, warp 32x64).
// Phase 1: T_tile[64 e][256 g] = Ws @ G  -> fp16 SMEM (pitch 528B).
// Phase 2: Pq[64 e][256 g']   = T_tile @ Ct.
// Load schedule hides Ct chunk0 under phase-1 chunk-1 compute and Ct chunk1
// under the T epilogue.
// ============================================================================
#define BUF23   87040
#define B23_OFF 17408
#define T23_OFF 174080
#define ROWB2   528
#define SMEM_23 207872

__global__ void __launch_bounds__(256)
k_s23()  // grid (et 4, 1, baq 32) = 128 CTAs
{
    extern __shared__ char smem[];
    const uint32_t sb  = smem_u32(smem);
    const int tid  = threadIdx.x;
    const int lane = tid & 31;
    const int wid  = tid >> 5;
    const int m0   = (wid & 1) * 32;
    const int n0   = (wid >> 1) * 64;
    const int et   = blockIdx.x;
    const int baq  = blockIdx.z;
    const int b = baq >> 4, a = (baq >> 2) & 3, q = baq & 3;
    const int aq = a * 4 + q, bq = b * 4 + q;

    const __half* Aw = g_Wc + (size_t)aq * 65536 + (size_t)et * 64 * 256;
    const __half* Bg = g_G  + (size_t)bq * 65536;
    const __half* Bc = g_Ct + (size_t)aq * 65536;

    const uint32_t aoff  = (uint32_t)(m0 + (lane & 15)) * ROWB + ((lane >> 4) << 4);
    const uint32_t aoff2 = (uint32_t)(m0 + (lane & 15)) * ROWB2 + ((lane >> 4) << 4);
    const uint32_t boff  = (uint32_t)(n0 + ((lane >> 4) << 3) + (lane & 7)) * ROWB
                         + ((lane & 8) ? 16u : 0u);
    const int rr = lane >> 2;
    const int cc = (lane & 3) * 2;

    float acc[2][8][4];

    auto load_A = [&](int c, const __half* A) {
        const uint32_t bo = sb + (uint32_t)(c & 1) * BUF23;
        const int k0 = c << 7;
#pragma unroll
        for (int i = 0; i < 4; i++) {
            int v = i * 256 + tid;
            int r = v >> 4, j = v & 15;
            cpa16(bo + (uint32_t)r * ROWB + (uint32_t)j * 16,
                  A + (size_t)r * 256 + k0 + j * 8);
        }
    };
    auto load_B = [&](int c, const __half* B) {
        const uint32_t bo = sb + (uint32_t)(c & 1) * BUF23 + B23_OFF;
        const int k0 = c << 7;
#pragma unroll
        for (int i = 0; i < 16; i++) {
            int v = i * 256 + tid;
            int r = v >> 4, j = v & 15;
            cpa16(bo + (uint32_t)r * ROWB + (uint32_t)j * 16,
                  B + (size_t)r * 256 + k0 + j * 8);
        }
    };
    auto zero_acc = [&]() {
#pragma unroll
        for (int i = 0; i < 2; i++)
#pragma unroll
            for (int j = 0; j < 8; j++)
#pragma unroll
                for (int r = 0; r < 4; r++) acc[i][j][r] = 0.0f;
    };
    auto mma_chunk = [&](uint32_t aP, uint32_t arowb, uint32_t bP) {
#pragma unroll
        for (int ks = 0; ks < 8; ks++) {
            const uint32_t ko = (uint32_t)ks * 32;
            uint32_t a0[4], a1[4];
            LDSM_X4(a0, aP + ko);
            LDSM_X4(a1, aP + 16 * arowb + ko);
            uint32_t br[4][4];
#pragma unroll
            for (int p = 0; p < 4; p++)
                LDSM_X4(br[p], bP + (uint32_t)p * 16 * ROWB + ko);
#pragma unroll
            for (int j = 0; j < 8; j++)
                MMA_F16(acc[0][j], a0, br[j >> 1][(j & 1) * 2], br[j >> 1][(j & 1) * 2 + 1]);
#pragma unroll
            for (int j = 0; j < 8; j++)
                MMA_F16(acc[1][j], a1, br[j >> 1][(j & 1) * 2], br[j >> 1][(j & 1) * 2 + 1]);
        }
    };

    // ---- phase 1: T_tile = Ws @ G ------------------------------------------
    zero_acc();
    load_A(0, Aw); load_B(0, Bg); CP_COMMIT();   // g0 -> buf0
    load_A(1, Aw); load_B(1, Bg); CP_COMMIT();   // g1 -> buf1
    CP_WAIT(1);
    __syncthreads();                              // g0 ready
    mma_chunk(sb + aoff, ROWB, sb + B23_OFF + boff);
    __syncthreads();                              // buf0 reads complete
    load_B(0, Bc); CP_COMMIT();                   // g2 -> buf0.B (Ct c0)
    CP_WAIT(1);                                   // g1 ready (g2 in flight)
    __syncthreads();
    mma_chunk(sb + BUF23 + aoff, ROWB, sb + BUF23 + B23_OFF + boff);
    __syncthreads();                              // buf1 reads complete

    load_B(1, Bc); CP_COMMIT();                   // g3 -> buf1.B (Ct c1)

    // T epilogue: fp16 into SMEM at T23_OFF (pitch 528B)
    {
        char* Tb = smem + T23_OFF;
#pragma unroll
        for (int i = 0; i < 2; i++) {
#pragma unroll
            for (int j = 0; j < 8; j++) {
                const int row = m0 + i * 16 + rr;
                const int col = n0 + j * 8 + cc;
                *(__half2*)(Tb + (size_t)row * ROWB2 + col * 2) =
                    __halves2half2(__float2half_rn(acc[i][j][0]), __float2half_rn(acc[i][j][1]));
                *(__half2*)(Tb + (size_t)(row + 8) * ROWB2 + col * 2) =
                    __halves2half2(__float2half_rn(acc[i][j][2]), __float2half_rn(acc[i][j][3]));
            }
        }
    }

    // ---- phase 2: Pq = T_tile @ Ct^T ---------------------------------------
    zero_acc();
    CP_WAIT(1);                                   // g2 ready (g3 in flight)
    __syncthreads();                              // + T_smem visible
    mma_chunk(sb + T23_OFF + aoff2, ROWB2, sb + B23_OFF + boff);
    CP_WAIT(0);                                   // g3 ready
    __syncthreads();
    mma_chunk(sb + T23_OFF + aoff2 + 256, ROWB2, sb + BUF23 + B23_OFF + boff);

    float* Cf = g_Pq + (size_t)baq * 65536 + (size_t)et * 64 * 256;
#pragma unroll
    for (int i = 0; i < 2; i++) {
#pragma unroll
        for (int j = 0; j < 8; j++) {
            const int row = m0 + i * 16 + rr;
            const int col = n0 + j * 8 + cc;
            float* p = Cf + (size_t)row * 256 + col;
            *(float2*)p = make_float2(acc[i][j][0], acc[i][j][1]);
            *(float2*)(p + 8 * 256) = make_float2(acc[i][j][2], acc[i][j][3]);
        }
    }
}

// ============================================================================
// s4: 128x256 tile (M=128 t-rows, N=256 g'), 8 warps as 2M x 4N (64x64 warp
// tile), BK=128 double-buffered. Single wave: grid (16, 1, 8) = 128 CTAs.
// SMEM: 2 x (A 128x272 + B 256x272) = 208896.
// ============================================================================
#define S4_B    34816
#define S4_BUF  104448
#define SMEM_S4 208896

__global__ void __launch_bounds__(256)
k_s4(float* __restrict__ out)
{
    extern __shared__ char smem[];
    const uint32_t sb  = smem_u32(smem);
    const int tid  = threadIdx.x;
    const int lane = tid & 31;
    const int wid  = tid >> 5;
    const int mw   = (wid >> 2) * 64;     // 2 M-warps
    const int nw   = (wid & 3) * 64;      // 4 N-warps
    const int mt = blockIdx.x, ba = blockIdx.z;
    const int b = ba >> 2, a = ba & 3;

    const __half* A = g_Xnt + (size_t)b * 2097152 + (size_t)mt * 128 * 1024 + a * 256;
    const __half* B = g_Pt + (size_t)ba * 65536;
    float* Cf = out + (size_t)b * 2097152 + (size_t)mt * 128 * 1024 + a * 256;

    const uint32_t aoff = (uint32_t)(mw + (lane & 15)) * ROWB + ((lane >> 4) << 4);
    const uint32_t boff = (uint32_t)(nw + ((lane >> 4) << 3) + (lane & 7)) * ROWB
                        + ((lane & 8) ? 16u : 0u);

    float acc[4][8][4];
#pragma unroll
    for (int i = 0; i < 4; i++)
#pragma unroll
        for (int j = 0; j < 8; j++)
#pragma unroll
            for (int r = 0; r < 4; r++) acc[i][j][r] = 0.0f;

    auto load_chunk = [&](int c) {
        const uint32_t bo = sb + (uint32_t)(c & 1) * S4_BUF;
        const int k0 = c << 7;
        // A: 128 rows x 16 vec16 -> 8 iters
#pragma unroll
        for (int i = 0; i < 8; i++) {
            int v = i * 256 + tid;
            int r = v >> 4, j = v & 15;
            cpa16(bo + (uint32_t)r * ROWB + (uint32_t)j * 16,
                  A + (size_t)r * 1024 + k0 + j * 8);
        }
        // B: 256 rows x 16 vec16 -> 16 iters
#pragma unroll
        for (int i = 0; i < 16; i++) {
            int v = i * 256 + tid;
            int r = v >> 4, j = v & 15;
            cpa16(bo + S4_B + (uint32_t)r * ROWB + (uint32_t)j * 16,
                  B + (size_t)r * 256 + k0 + j * 8);
        }
    };

    load_chunk(0);
    CP_COMMIT();

#pragma unroll 1
    for (int c = 0; c < 2; c++) {
        if (c == 0) { load_chunk(1); CP_COMMIT(); CP_WAIT(1); }
        else        { CP_WAIT(0); }
        __syncthreads();

        const uint32_t bo = sb + (uint32_t)(c & 1) * S4_BUF;
        const uint32_t aP = bo + aoff;
        const uint32_t bP = bo + S4_B + boff;

#pragma unroll
        for (int ks = 0; ks < 8; ks++) {
            const uint32_t ko = (uint32_t)ks * 32;
            uint32_t af[4][4];
#pragma unroll
            for (int i = 0; i < 4; i++)
                LDSM_X4(af[i], aP + (uint32_t)i * 16 * ROWB + ko);
            uint32_t br[4][4];
#pragma unroll
            for (int p = 0; p < 4; p++)
                LDSM_X4(br[p], bP + (uint32_t)p * 16 * ROWB + ko);
#pragma unroll
            for (int i = 0; i < 4; i++)
#pragma unroll
                for (int j = 0; j < 8; j++)
                    MMA_F16(acc[i][j], af[i], br[j >> 1][(j & 1) * 2], br[j >> 1][(j & 1) * 2 + 1]);
        }
        __syncthreads();
    }

    const int rr = lane >> 2;
    const int cc = (lane & 3) * 2;
    const float ds = 1.0f / 1024.0f;
#pragma unroll
    for (int i = 0; i < 4; i++) {
#pragma unroll
        for (int j = 0; j < 8; j++) {
            const int row = mw + i * 16 + rr;
            const int col = nw + j * 8 + cc;
            float* p = Cf + (size_t)row * 1024 + col;
            *(float2*)p = make_float2(acc[i][j][0] * ds, acc[i][j][1] * ds);
            *(float2*)(p + (size_t)8 * 1024) =
                make_float2(acc[i][j][2] * ds, acc[i][j][3] * ds);
        }
    }
}

// ============================================================================
// fused conversion kernel: grid 6144 blocks x 256
// ============================================================================
__global__ void k_conv(const float* __restrict__ hid,
                       const float* __restrict__ qr,
                       const float* __restrict__ cb)
{
    __shared__ float ts[32][33];
    const int blk = blockIdx.x;
    const int tid = threadIdx.x;

    if (blk < 4096) {
        int i = blk;                                     // 8 x 64 x 8
        int fb = i & 7, tb = (i >> 3) & 63, bq = i >> 9;
        int b = bq >> 2, q = bq & 3;
        int t0 = tb * 32, f0 = fb * 32;
        int tx = tid & 31, ty = tid >> 5;
#pragma unroll
        for (int r = 0; r < 4; r++) {
            int tt = t0 + ty + r * 8;
            float v = hid[(size_t)b * 2097152 + (size_t)tt * 1024 + q * 256 + f0 + tx];
            ts[ty + r * 8][tx] = v;
            g_Xnt[(size_t)b * 2097152 + (size_t)tt * 1024 + q * 256 + f0 + tx] =
                __float2half_rn(v);
        }
        __syncthreads();
#pragma unroll
        for (int r = 0; r < 4; r++) {
            int f = f0 + ty + r * 8;
            int tw = t0 + tx;
            g_Xt[(size_t)bq * 524288 + (size_t)f * 2048 + tw] =
                __float2half_rn(ts[tx][ty + r * 8]);
        }
    } else if (blk < 5120) {
        int o4 = (blk - 4096) * 256 + tid;               // 262144 float4s
        int aq = o4 >> 14;
        int rem = (o4 << 2) & 65535;
        int e = rem >> 8, f = rem & 255;
        int a = aq >> 2, q = aq & 3;
        float4 v = *(const float4*)(qr + (size_t)a * 262144 + (size_t)e * 1024 + q * 256 + f);
        v.x *= 1024.f; v.y *= 1024.f; v.z *= 1024.f; v.w *= 1024.f;
        ((uint2*)g_Wc)[o4] = pack4H(v);
    } else {
        int i = blk - 5120;                              // 8 x 8 x 16
        int gpb = i & 7, gb = (i >> 3) & 7, aq = i >> 6;
        int a = aq >> 2, q = aq & 3;
        int g0 = gb * 32, gp0 = gpb * 32;
        int tx = tid & 31, ty = tid >> 5;
#pragma unroll
        for (int r = 0; r < 4; r++) {
            int g = g0 + ty + r * 8;
            ts[ty + r * 8][tx] =
                cb[(size_t)a * 262144 + (size_t)(q * 256 + g) * 256 + gp0 + tx] * 1024.f;
        }
        __syncthreads();
#pragma unroll
        for (int r = 0; r < 4; r++) {
            int gp = gp0 + ty + r * 8;
            int gw = g0 + tx;
            g_Ct[(size_t)aq * 65536 + (size_t)gp * 256 + gw] =
                __float2half_rn(ts[tx][ty + r * 8]);
        }
    }
}

// ---- reduce Gram partials (6 chunks, 3 tiles) + mirror + fp16 ---------------
__global__ void k_reduceG()
{
    __shared__ float s[32][33];
    const int sub = blockIdx.x, t = blockIdx.y, bq = blockIdx.z;
    const int r0 = (sub >> 2) * 32, c0 = (sub & 3) * 32;
    const int tx = threadIdx.x & 31, ty = threadIdx.x >> 5;

    const int br = (t == 2) ? 128 : 0;
    const int bc = (t == 0) ? 0 : 128;
    float v[4];
#pragma unroll
    for (int k = 0; k < 4; k++) {
        const int r = r0 + ty + k * 8;
        float a = 0.f;
#pragma unroll
        for (int ch = 0; ch < 6; ch++)
            a += g_Gpart[(size_t)((ch * 8 + bq) * 3 + t) * 16384 + r * 128 + c0 + tx];
        v[k] = a;
        s[ty + k * 8][tx] = a;
    }
#pragma unroll
    for (int k = 0; k < 4; k++) {
        size_t o = (size_t)bq * 65536 + (size_t)(br + r0 + ty + k * 8) * 256 + bc + c0 + tx;
        g_G[o] = __float2half_rn(v[k]);
    }
    if (t == 1) {
        __syncthreads();
#pragma unroll
        for (int k = 0; k < 4; k++) {
            const int orow = 128 + c0 + ty + k * 8;
            const int ocol = r0 + tx;
            g_G[(size_t)bq * 65536 + (size_t)orow * 256 + ocol] =
                __float2half_rn(s[tx][ty + k * 8]);
        }
    }
}

// ---- reduce Pq over q + transpose + descale 2^-10 + fp16 --------------------
__global__ void k_reduceP()
{
    __shared__ float t[32][33];
    const int ba = blockIdx.z, b = ba >> 2, a = ba & 3;
    const int e0 = blockIdx.y * 32, gp0 = blockIdx.x * 32;
    const int tx = threadIdx.x & 31, ty = threadIdx.x >> 5;
#pragma unroll
    for (int r = 0; r < 4; r++) {
        const int e = e0 + ty + r * 8;
        float s = 0.f;
#pragma unroll
        for (int q = 0; q < 4; q++)
            s += g_Pq[(size_t)(b * 16 + a * 4 + q) * 65536 + (size_t)e * 256 + gp0 + tx];
        t[ty + r * 8][tx] = s;
    }
    __syncthreads();
    const float ds = 1.0f / 1024.0f;
#pragma unroll
    for (int r = 0; r < 4; r++) {
        const int gp = gp0 + ty + r * 8;
        const int ew = e0 + tx;
        g_Pt[(size_t)ba * 65536 + (size_t)gp * 256 + ew] =
            __float2half_rn(t[tx][ty + r * 8] * ds);
    }
}

// ============================================================================
// s1 stage kernel
// ============================================================================
__global__ void __launch_bounds__(256)
k_s1()  // Gram, symmetric: grid (tile 3, chunk 6, bq 8) = 144 CTAs
{
    const int t  = blockIdx.x;                 // 0:(0,0) 1:(0,1) 2:(1,1)
    const int ch = blockIdx.y, bq = blockIdx.z;
    const int mt = (t == 2) ? 1 : 0;
    const int nt = (t == 0) ? 0 : 1;
    const int k0 = (ch < 4) ? ch * 384 : 1536 + (ch - 4) * 256;
    const int K  = (ch < 4) ? 384 : 256;

    size_t xo = (size_t)bq * 524288;
    const __half* A = g_Xt + xo + (size_t)mt * 128 * 2048 + k0;
    const __half* B = g_Xt + xo + (size_t)nt * 128 * 2048 + k0;
    float* Cf = g_Gpart + (size_t)((ch * 8 + bq) * 3 + t) * 16384;
    gemm128(A, 2048, B, 2048, K, Cf, 128, 1.0f);
}

// ============================================================================
extern "C" void kernel_launch(void* const* d_in, const int* in_sizes, int n_in,
                              void* d_out, int out_size)
{
    const float* hidden    = (const float*)d_in[0];  // [2,2048,1024]
    const float* queries   = (const float*)d_in[1];  // [4,256,1024]
    const float* combiners = (const float*)d_in[2];  // [4,1024,256]
    float* out = (float*)d_out;
    (void)in_sizes; (void)n_in; (void)out_size;

    cudaFuncSetAttribute(k_s1,  cudaFuncAttributeMaxDynamicSharedMemorySize, SMEM_G);
    cudaFuncSetAttribute(k_s23, cudaFuncAttributeMaxDynamicSharedMemorySize, SMEM_23);
    cudaFuncSetAttribute(k_s4,  cudaFuncAttributeMaxDynamicSharedMemorySize, SMEM_S4);

    k_conv<<<6144, 256>>>(hidden, queries, combiners);
    k_s1<<<dim3(3, 6, 8), 256, SMEM_G>>>();
    k_reduceG<<<dim3(16, 3, 8), 256>>>();
    k_s23<<<dim3(4, 1, 32), 256, SMEM_23>>>();
    k_reduceP<<<dim3(8, 8, 8), 256>>>();
    k_s4<<<dim3(16, 1, 8), 256, SMEM_S4>>>(out);
}